// round 6
// baseline (speedup 1.0000x reference)
#include <cuda_runtime.h>
#include <math.h>

// ---------------- problem constants ----------------
namespace {
constexpr int Bb = 2, Tt = 2048, Dd = 1024;
constexpr int NH = 16, DH = 64, CH = 80;
constexpr int RQ = 6, RK = 2, RV = 2;
constexpr int M  = Bb * Tt;            // 4096 rows
constexpr int NQ = RQ * CH;            // 480
constexpr int NKV = (RK + RV) * CH;    // 320
}

// ---------------- scratch (device globals; no cudaMalloc allowed) ----------------
__device__ __align__(16) float g_abq [M * NQ];
__device__ __align__(16) float g_abkv[M * NKV];
__device__ __align__(16) float g_q[Bb * NH * Tt * DH];
__device__ __align__(16) float g_k[Bb * NH * Tt * DH];
__device__ __align__(16) float g_v[Bb * NH * Tt * DH];
__device__ __align__(16) float g_y[M * Dd];

// ============================================================================
// SGEMM (NT): C[M,N] = A[M,K] @ B[N,K]^T   (both operands K-contiguous)
// 128x128 block tile, BK=16, 256 threads, 8x8 register micro-tile.
// B-columns are assigned interleaved (tx + 16*j) so the 8 per-k B reads are
// conflict-free scalar LDS; A reads are half-warp broadcasts (LDS.128).
// ============================================================================
__global__ __launch_bounds__(256) void sgemm_nt(const float* __restrict__ A,
                                                const float* __restrict__ Bm,
                                                float* __restrict__ C,
                                                int Mn, int Nn, int Kn)
{
    __shared__ float As[16][132];   // [k][m], padded
    __shared__ float Bs[16][132];   // [k][n], padded

    const int tid = threadIdx.x;
    const int tx = tid & 15, ty = tid >> 4;
    const int m0 = blockIdx.y * 128;
    const int n0 = blockIdx.x * 128;

    float acc[8][8];
    #pragma unroll
    for (int i = 0; i < 8; i++)
        #pragma unroll
        for (int j = 0; j < 8; j++) acc[i][j] = 0.f;

    for (int k0 = 0; k0 < Kn; k0 += 16) {
        // load A tile 128x16 (always in-bounds: M multiple of 128)
        #pragma unroll
        for (int i = 0; i < 2; i++) {
            int l = tid + i * 256;
            int r = l >> 2, c4 = (l & 3) << 2;
            float4 av = *(const float4*)(A + (size_t)(m0 + r) * Kn + k0 + c4);
            As[c4 + 0][r] = av.x; As[c4 + 1][r] = av.y;
            As[c4 + 2][r] = av.z; As[c4 + 3][r] = av.w;
        }
        // load B tile 128x16 with N-bounds guard
        #pragma unroll
        for (int i = 0; i < 2; i++) {
            int l = tid + i * 256;
            int r = l >> 2, c4 = (l & 3) << 2;
            float4 bv = make_float4(0.f, 0.f, 0.f, 0.f);
            if (n0 + r < Nn)
                bv = *(const float4*)(Bm + (size_t)(n0 + r) * Kn + k0 + c4);
            Bs[c4 + 0][r] = bv.x; Bs[c4 + 1][r] = bv.y;
            Bs[c4 + 2][r] = bv.z; Bs[c4 + 3][r] = bv.w;
        }
        __syncthreads();

        #pragma unroll
        for (int kk = 0; kk < 16; kk++) {
            float a[8], b[8];
            float4 a0 = *(const float4*)&As[kk][ty << 3];
            float4 a1 = *(const float4*)&As[kk][(ty << 3) + 4];
            a[0] = a0.x; a[1] = a0.y; a[2] = a0.z; a[3] = a0.w;
            a[4] = a1.x; a[5] = a1.y; a[6] = a1.z; a[7] = a1.w;
            #pragma unroll
            for (int j = 0; j < 8; j++) b[j] = Bs[kk][tx + (j << 4)];
            #pragma unroll
            for (int i = 0; i < 8; i++)
                #pragma unroll
                for (int j = 0; j < 8; j++)
                    acc[i][j] = fmaf(a[i], b[j], acc[i][j]);
        }
        __syncthreads();
    }

    #pragma unroll
    for (int i = 0; i < 8; i++) {
        int row = m0 + (ty << 3) + i;
        #pragma unroll
        for (int j = 0; j < 8; j++) {
            int col = n0 + tx + (j << 4);
            if (col < Nn) C[(size_t)row * Nn + col] = acc[i][j];
        }
    }
}

// ============================================================================
// build_qkv: per (b,t) row — RoPE on the KV b-parts, then contract the rank
// dimension to produce q/k/v in [B*H][T][DH] layout for attention.
// ============================================================================
__global__ __launch_bounds__(128) void build_qkv()
{
    const int bt = blockIdx.x;          // 0..4095
    const int b = bt / Tt, t = bt % Tt;
    const int tid = threadIdx.x;

    __shared__ float sq [NQ];   // 480
    __shared__ float skv[NKV];  // 320

    for (int i = tid; i < NQ;  i += 128) sq[i]  = g_abq [(size_t)bt * NQ  + i];
    for (int i = tid; i < NKV; i += 128) skv[i] = g_abkv[(size_t)bt * NKV + i];
    __syncthreads();

    // rotary on all 4 KV ranks' b-parts: 4 ranks * 32 pairs = 128 items
    {
        const int rr = tid >> 5, d = tid & 31;
        // inv_freq = (1/10000)^(d/32)
        const float inv = __expf(-(float)d * (9.2103403719761836f / 32.0f));
        const float fr  = (float)t * inv;
        const float c = cosf(fr), s = sinf(fr);
        const int base = rr * CH + NH;
        const float x1 = skv[base + d];
        const float x2 = skv[base + 32 + d];
        skv[base + d]      =  x1 * c + x2 * s;
        skv[base + 32 + d] = -x1 * s + x2 * c;
    }
    __syncthreads();

    // q[h][d] = (1/RQ) * sum_r a_q[r][h] * b_q[r][d]   (no rotary on q)
    for (int o = tid; o < NH * DH; o += 128) {
        const int h = o >> 6, dd = o & 63;
        float acc = 0.f;
        #pragma unroll
        for (int r = 0; r < RQ; r++)
            acc = fmaf(sq[r * CH + h], sq[r * CH + NH + dd], acc);
        g_q[(((size_t)(b * NH + h)) * Tt + t) * DH + dd] = acc * (1.0f / RQ);
    }
    // k: KV ranks 0,1 ; v: KV ranks 2,3 (rotated b-parts)
    for (int o = tid; o < NH * DH; o += 128) {
        const int h = o >> 6, dd = o & 63;
        float ak = fmaf(skv[0 * CH + h], skv[0 * CH + NH + dd],
                        skv[1 * CH + h] * skv[1 * CH + NH + dd]);
        float av = fmaf(skv[2 * CH + h], skv[2 * CH + NH + dd],
                        skv[3 * CH + h] * skv[3 * CH + NH + dd]);
        const size_t idx = (((size_t)(b * NH + h)) * Tt + t) * DH + dd;
        g_k[idx] = ak * 0.5f;
        g_v[idx] = av * 0.5f;
    }
}

// ============================================================================
// Causal flash attention, fp32. Grid: (T/64 q-tiles, B*H). 256 threads.
// 64x64 tiles; Q/K stored transposed [d][row] in smem so compute-phase LDS.128
// are conflict-free; P overwrites the K buffer (total static smem exactly 48KB).
// Row r is owned by half-warp {ty = r/4}; softmax reductions via shfl_xor<16.
// ============================================================================
__global__ __launch_bounds__(256) void attn_kernel()
{
    __shared__ float Qst[64][64];   // [d][row], pre-scaled by 1/sqrt(DH)
    __shared__ float KPs[64][64];   // K as [d][col]; then P as [row][col]
    __shared__ float Vs [64][64];   // [row(j)][d]

    const int tid = threadIdx.x;
    const int tx = tid & 15, ty = tid >> 4;
    const int qt = blockIdx.x, bh = blockIdx.y;
    const float* qp = g_q + (size_t)bh * Tt * DH;
    const float* kp = g_k + (size_t)bh * Tt * DH;
    const float* vp = g_v + (size_t)bh * Tt * DH;
    const int q0 = qt * 64;

    #pragma unroll
    for (int i = 0; i < 4; i++) {
        int l = tid + i * 256;
        int r = l >> 4, d4 = (l & 15) << 2;
        float4 qv = *(const float4*)(qp + (size_t)(q0 + r) * DH + d4);
        Qst[d4 + 0][r] = qv.x * 0.125f;
        Qst[d4 + 1][r] = qv.y * 0.125f;
        Qst[d4 + 2][r] = qv.z * 0.125f;
        Qst[d4 + 3][r] = qv.w * 0.125f;
    }

    float m[4], l_[4], O[4][4];
    #pragma unroll
    for (int i = 0; i < 4; i++) {
        m[i] = -1e30f; l_[i] = 0.f;
        O[i][0] = O[i][1] = O[i][2] = O[i][3] = 0.f;
    }

    for (int kt = 0; kt <= qt; kt++) {
        const int k0 = kt * 64;
        __syncthreads();   // prior tile's P/V reads done; also orders Q writes
        #pragma unroll
        for (int i = 0; i < 4; i++) {
            int l = tid + i * 256;
            int r = l >> 4, d4 = (l & 15) << 2;
            float4 kv = *(const float4*)(kp + (size_t)(k0 + r) * DH + d4);
            KPs[d4 + 0][r] = kv.x; KPs[d4 + 1][r] = kv.y;
            KPs[d4 + 2][r] = kv.z; KPs[d4 + 3][r] = kv.w;
            *(float4*)&Vs[r][d4] = *(const float4*)(vp + (size_t)(k0 + r) * DH + d4);
        }
        __syncthreads();

        // S = (Q*scale) K^T   (4x4 micro-tile per thread)
        float s[4][4];
        #pragma unroll
        for (int i = 0; i < 4; i++)
            #pragma unroll
            for (int j = 0; j < 4; j++) s[i][j] = 0.f;

        #pragma unroll 16
        for (int d = 0; d < 64; d++) {
            float4 q4 = *(const float4*)&Qst[d][ty << 2];
            float4 k4 = *(const float4*)&KPs[d][tx << 2];
            const float qa[4] = {q4.x, q4.y, q4.z, q4.w};
            const float kb[4] = {k4.x, k4.y, k4.z, k4.w};
            #pragma unroll
            for (int i = 0; i < 4; i++)
                #pragma unroll
                for (int j = 0; j < 4; j++)
                    s[i][j] = fmaf(qa[i], kb[j], s[i][j]);
        }

        if (kt == qt) {  // diagonal tile: mask j > i
            #pragma unroll
            for (int i = 0; i < 4; i++)
                #pragma unroll
                for (int j = 0; j < 4; j++)
                    if ((tx << 2) + j > (ty << 2) + i) s[i][j] = -1e30f;
        }

        // online softmax per row (16-lane groups)
        #pragma unroll
        for (int i = 0; i < 4; i++) {
            float tm = fmaxf(fmaxf(s[i][0], s[i][1]), fmaxf(s[i][2], s[i][3]));
            #pragma unroll
            for (int o = 8; o > 0; o >>= 1)
                tm = fmaxf(tm, __shfl_xor_sync(0xffffffffu, tm, o));
            float mn = fmaxf(m[i], tm);
            float alpha = __expf(m[i] - mn);
            m[i] = mn;
            float tl = 0.f;
            #pragma unroll
            for (int j = 0; j < 4; j++) {
                s[i][j] = __expf(s[i][j] - mn);
                tl += s[i][j];
            }
            #pragma unroll
            for (int o = 8; o > 0; o >>= 1)
                tl += __shfl_xor_sync(0xffffffffu, tl, o);
            l_[i] = l_[i] * alpha + tl;
            #pragma unroll
            for (int e = 0; e < 4; e++) O[i][e] *= alpha;
        }

        __syncthreads();   // everyone done reading K from KPs
        #pragma unroll
        for (int i = 0; i < 4; i++)
            *(float4*)&KPs[(ty << 2) + i][tx << 2] =
                make_float4(s[i][0], s[i][1], s[i][2], s[i][3]);
        __syncthreads();

        // O += P V
        #pragma unroll 4
        for (int j4 = 0; j4 < 16; j4++) {
            float vv[4][4];
            #pragma unroll
            for (int jj = 0; jj < 4; jj++) {
                float4 v4 = *(const float4*)&Vs[(j4 << 2) + jj][tx << 2];
                vv[jj][0] = v4.x; vv[jj][1] = v4.y; vv[jj][2] = v4.z; vv[jj][3] = v4.w;
            }
            #pragma unroll
            for (int i = 0; i < 4; i++) {
                float4 p4 = *(const float4*)&KPs[(ty << 2) + i][j4 << 2];
                const float pp[4] = {p4.x, p4.y, p4.z, p4.w};
                #pragma unroll
                for (int e = 0; e < 4; e++) {
                    float acc = O[i][e];
                    acc = fmaf(pp[0], vv[0][e], acc);
                    acc = fmaf(pp[1], vv[1][e], acc);
                    acc = fmaf(pp[2], vv[2][e], acc);
                    acc = fmaf(pp[3], vv[3][e], acc);
                    O[i][e] = acc;
                }
            }
        }
    }

    // epilogue: normalize + write y in [B,T,H*DH] layout
    const int b = bh >> 4, h = bh & 15;
    #pragma unroll
    for (int i = 0; i < 4; i++) {
        const float inv = 1.0f / l_[i];
        const int t = q0 + (ty << 2) + i;
        float4 o4 = make_float4(O[i][0] * inv, O[i][1] * inv,
                                O[i][2] * inv, O[i][3] * inv);
        *(float4*)(g_y + ((size_t)b * Tt + t) * Dd + h * DH + (tx << 2)) = o4;
    }
}

// ============================================================================
// launch
// ============================================================================
extern "C" void kernel_launch(void* const* d_in, const int* in_sizes, int n_in,
                              void* d_out, int out_size)
{
    const float* x      = (const float*)d_in[0];   // [B,T,D]
    const float* W_abq  = (const float*)d_in[1];   // [480,1024]
    const float* W_abkv = (const float*)d_in[2];   // [320,1024]
    const float* W_o    = (const float*)d_in[3];   // [1024,1024]
    float* out = (float*)d_out;                    // [B,T,D]

    float *abq, *abkv, *yb;
    cudaGetSymbolAddress((void**)&abq,  g_abq);
    cudaGetSymbolAddress((void**)&abkv, g_abkv);
    cudaGetSymbolAddress((void**)&yb,   g_y);

    {   // x @ W_abq^T  -> abq [4096,480]
        dim3 grid((NQ + 127) / 128, M / 128);
        sgemm_nt<<<grid, 256>>>(x, W_abq, abq, M, NQ, Dd);
    }
    {   // x @ W_abkv^T -> abkv [4096,320]
        dim3 grid((NKV + 127) / 128, M / 128);
        sgemm_nt<<<grid, 256>>>(x, W_abkv, abkv, M, NKV, Dd);
    }
    build_qkv<<<M, 128>>>();
    {
        dim3 grid(Tt / 64, Bb * NH);
        attn_kernel<<<grid, 256>>>();
    }
    {   // y @ W_o^T -> out [4096,1024]
        dim3 grid(Dd / 128, M / 128);
        sgemm_nt<<<grid, 256>>>(yb, W_o, out, M, Dd, Dd);
    }
}

// round 12
// speedup vs baseline: 2.3656x; 2.3656x over previous
#include <cuda_runtime.h>
#include <math.h>

// ---------------- problem constants ----------------
namespace {
constexpr int Bb = 2, Tt = 2048, Dd = 1024;
constexpr int NH = 16, DH = 64, CH = 80;
constexpr int RQ = 6, RK = 2, RV = 2;
constexpr int M  = Bb * Tt;            // 4096 rows
constexpr int NQ = RQ * CH;            // 480
constexpr int NKV = (RK + RV) * CH;    // 320
}

// ---------------- scratch (device globals; no cudaMalloc allowed) ----------------
__device__ __align__(16) float g_abq [M * NQ];
__device__ __align__(16) float g_abkv[M * NKV];
__device__ __align__(16) float g_q[Bb * NH * Tt * DH];
__device__ __align__(16) float g_k[Bb * NH * Tt * DH];
__device__ __align__(16) float g_v[Bb * NH * Tt * DH];
__device__ __align__(16) float g_y[M * Dd];

// ---------------- tf32 helpers ----------------
__device__ __forceinline__ unsigned tf32u(float x) {
    unsigned u;
    asm("cvt.rna.tf32.f32 %0, %1;" : "=r"(u) : "f"(x));
    return u;
}
__device__ __forceinline__ float tf32f(float x) { return __uint_as_float(tf32u(x)); }

// D += A(16x8) * B(8x8), tf32 in, fp32 accumulate
__device__ __forceinline__ void mma_tf32(float c[4], const unsigned a[4], const unsigned b[2]) {
    asm volatile(
        "mma.sync.aligned.m16n8k8.row.col.f32.tf32.tf32.f32 "
        "{%0,%1,%2,%3},{%4,%5,%6,%7},{%8,%9},{%0,%1,%2,%3};"
        : "+f"(c[0]), "+f"(c[1]), "+f"(c[2]), "+f"(c[3])
        : "r"(a[0]), "r"(a[1]), "r"(a[2]), "r"(a[3]), "r"(b[0]), "r"(b[1]));
}

// ============================================================================
// build_qkv: RoPE + rank contraction
// ============================================================================
__global__ __launch_bounds__(128) void build_qkv()
{
    const int bt = blockIdx.x;
    const int b = bt / Tt, t = bt % Tt;
    const int tid = threadIdx.x;

    __shared__ float sq [NQ];
    __shared__ float skv[NKV];

    for (int i = tid; i < NQ;  i += 128) sq[i]  = g_abq [(size_t)bt * NQ  + i];
    for (int i = tid; i < NKV; i += 128) skv[i] = g_abkv[(size_t)bt * NKV + i];
    __syncthreads();

    {
        const int rr = tid >> 5, d = tid & 31;
        const float inv = __expf(-(float)d * (9.2103403719761836f / 32.0f));
        const float fr  = (float)t * inv;
        const float c = cosf(fr), s = sinf(fr);
        const int base = rr * CH + NH;
        const float x1 = skv[base + d];
        const float x2 = skv[base + 32 + d];
        skv[base + d]      =  x1 * c + x2 * s;
        skv[base + 32 + d] = -x1 * s + x2 * c;
    }
    __syncthreads();

    for (int o = tid; o < NH * DH; o += 128) {
        const int h = o >> 6, dd = o & 63;
        float acc = 0.f;
        #pragma unroll
        for (int r = 0; r < RQ; r++)
            acc = fmaf(sq[r * CH + h], sq[r * CH + NH + dd], acc);
        g_q[(((size_t)(b * NH + h)) * Tt + t) * DH + dd] = acc * (1.0f / RQ);
    }
    for (int o = tid; o < NH * DH; o += 128) {
        const int h = o >> 6, dd = o & 63;
        float ak = fmaf(skv[0 * CH + h], skv[0 * CH + NH + dd],
                        skv[1 * CH + h] * skv[1 * CH + NH + dd]);
        float av = fmaf(skv[2 * CH + h], skv[2 * CH + NH + dd],
                        skv[3 * CH + h] * skv[3 * CH + NH + dd]);
        const size_t idx = (((size_t)(b * NH + h)) * Tt + t) * DH + dd;
        g_k[idx] = ak * 0.5f;
        g_v[idx] = av * 0.5f;
    }
}

// ============================================================================
// Causal flash attention with TF32 mma.sync (m16n8k8), fp32 accumulate.
// 64 q-rows per block, 4 warps (16 q-rows each). Q fragments live in regs for
// the whole block. K tile buffer is reused as the P (probabilities) buffer.
// grid = (32 bh, 32 qtile-slots), qt reversed for LPT scheduling.
// ============================================================================
__global__ __launch_bounds__(128) void attn_mma()
{
    __shared__ float Ks[64][68];   // K tile [kcol][d]; later P [w*16+row][j]
    __shared__ float Vs[64][72];   // V tile [j][d]

    const int tid  = threadIdx.x;
    const int lane = tid & 31;
    const int w    = tid >> 5;
    const int g    = lane >> 2;    // group id (row within fragment)
    const int t    = lane & 3;     // thread-in-group (col within fragment)
    const int bh   = blockIdx.x;
    const int qt   = ((int)gridDim.y - 1) - (int)blockIdx.y;  // longest first
    const int q0   = qt * 64;

    const float* qp = g_q + (size_t)bh * Tt * DH;
    const float* kp = g_k + (size_t)bh * Tt * DH;
    const float* vp = g_v + (size_t)bh * Tt * DH;

    // ---- stage Q (pre-scaled by 1/sqrt(DH)) into Ks, pull fragments to regs
    #pragma unroll
    for (int i = 0; i < 8; i++) {
        int l = tid + i * 128;
        int r = l >> 4, d4 = (l & 15) << 2;
        float4 qv = *(const float4*)(qp + (size_t)(q0 + r) * DH + d4);
        Ks[r][d4 + 0] = tf32f(qv.x * 0.125f);
        Ks[r][d4 + 1] = tf32f(qv.y * 0.125f);
        Ks[r][d4 + 2] = tf32f(qv.z * 0.125f);
        Ks[r][d4 + 3] = tf32f(qv.w * 0.125f);
    }
    __syncthreads();
    unsigned Qa[8][4];
    #pragma unroll
    for (int dk = 0; dk < 8; dk++) {
        Qa[dk][0] = __float_as_uint(Ks[w * 16 + g    ][dk * 8 + t    ]);
        Qa[dk][1] = __float_as_uint(Ks[w * 16 + g + 8][dk * 8 + t    ]);
        Qa[dk][2] = __float_as_uint(Ks[w * 16 + g    ][dk * 8 + t + 4]);
        Qa[dk][3] = __float_as_uint(Ks[w * 16 + g + 8][dk * 8 + t + 4]);
    }

    float O[8][4];
    #pragma unroll
    for (int n = 0; n < 8; n++) { O[n][0] = O[n][1] = O[n][2] = O[n][3] = 0.f; }
    float m0 = -1e30f, m1 = -1e30f, l0 = 0.f, l1 = 0.f;

    for (int kt = 0; kt <= qt; kt++) {
        const int k0 = kt * 64;
        __syncthreads();   // previous iter's P/V reads complete (and Q frag reads)
        #pragma unroll
        for (int i = 0; i < 8; i++) {
            int l = tid + i * 128;
            int r = l >> 4, d4 = (l & 15) << 2;
            float4 kv = *(const float4*)(kp + (size_t)(k0 + r) * DH + d4);
            Ks[r][d4 + 0] = tf32f(kv.x);
            Ks[r][d4 + 1] = tf32f(kv.y);
            Ks[r][d4 + 2] = tf32f(kv.z);
            Ks[r][d4 + 3] = tf32f(kv.w);
            float4 vv = *(const float4*)(vp + (size_t)(k0 + r) * DH + d4);
            Vs[r][d4 + 0] = tf32f(vv.x);
            Vs[r][d4 + 1] = tf32f(vv.y);
            Vs[r][d4 + 2] = tf32f(vv.z);
            Vs[r][d4 + 3] = tf32f(vv.w);
        }
        __syncthreads();

        // ---- S = Q K^T : 8 n-tiles x 8 k(d)-steps of mma
        float c[8][4];
        #pragma unroll
        for (int n = 0; n < 8; n++) { c[n][0] = c[n][1] = c[n][2] = c[n][3] = 0.f; }
        #pragma unroll
        for (int dk = 0; dk < 8; dk++) {
            #pragma unroll
            for (int n = 0; n < 8; n++) {
                unsigned bb[2] = { __float_as_uint(Ks[n * 8 + g][dk * 8 + t]),
                                   __float_as_uint(Ks[n * 8 + g][dk * 8 + t + 4]) };
                mma_tf32(c[n], Qa[dk], bb);
            }
        }

        if (kt == qt) {   // causal mask on diagonal tile
            const int r0 = w * 16 + g, r1 = r0 + 8;
            #pragma unroll
            for (int n = 0; n < 8; n++) {
                const int cb = n * 8 + 2 * t;
                if (cb     > r0) c[n][0] = -1e30f;
                if (cb + 1 > r0) c[n][1] = -1e30f;
                if (cb     > r1) c[n][2] = -1e30f;
                if (cb + 1 > r1) c[n][3] = -1e30f;
            }
        }

        // ---- online softmax (rows g and g+8; 4-lane row groups)
        float tm0 = -1e30f, tm1 = -1e30f;
        #pragma unroll
        for (int n = 0; n < 8; n++) {
            tm0 = fmaxf(tm0, fmaxf(c[n][0], c[n][1]));
            tm1 = fmaxf(tm1, fmaxf(c[n][2], c[n][3]));
        }
        #pragma unroll
        for (int o = 1; o < 4; o <<= 1) {
            tm0 = fmaxf(tm0, __shfl_xor_sync(0xffffffffu, tm0, o));
            tm1 = fmaxf(tm1, __shfl_xor_sync(0xffffffffu, tm1, o));
        }
        const float mn0 = fmaxf(m0, tm0), mn1 = fmaxf(m1, tm1);
        const float al0 = __expf(m0 - mn0), al1 = __expf(m1 - mn1);
        m0 = mn0; m1 = mn1;
        float tl0 = 0.f, tl1 = 0.f;
        #pragma unroll
        for (int n = 0; n < 8; n++) {
            c[n][0] = __expf(c[n][0] - mn0);  tl0 += c[n][0];
            c[n][1] = __expf(c[n][1] - mn0);  tl0 += c[n][1];
            c[n][2] = __expf(c[n][2] - mn1);  tl1 += c[n][2];
            c[n][3] = __expf(c[n][3] - mn1);  tl1 += c[n][3];
        }
        #pragma unroll
        for (int o = 1; o < 4; o <<= 1) {
            tl0 += __shfl_xor_sync(0xffffffffu, tl0, o);
            tl1 += __shfl_xor_sync(0xffffffffu, tl1, o);
        }
        l0 = l0 * al0 + tl0;
        l1 = l1 * al1 + tl1;
        #pragma unroll
        for (int n = 0; n < 8; n++) {
            O[n][0] *= al0; O[n][1] *= al0;
            O[n][2] *= al1; O[n][3] *= al1;
        }

        __syncthreads();   // all warps finished reading K from Ks
        // ---- write P (tf32) into this warp's Ks chunk
        #pragma unroll
        for (int n = 0; n < 8; n++) {
            *(float2*)&Ks[w * 16 + g    ][n * 8 + 2 * t] =
                make_float2(tf32f(c[n][0]), tf32f(c[n][1]));
            *(float2*)&Ks[w * 16 + g + 8][n * 8 + 2 * t] =
                make_float2(tf32f(c[n][2]), tf32f(c[n][3]));
        }
        __syncwarp();

        // ---- O += P V
        #pragma unroll
        for (int kj = 0; kj < 8; kj++) {
            unsigned pa[4];
            pa[0] = __float_as_uint(Ks[w * 16 + g    ][kj * 8 + t    ]);
            pa[1] = __float_as_uint(Ks[w * 16 + g + 8][kj * 8 + t    ]);
            pa[2] = __float_as_uint(Ks[w * 16 + g    ][kj * 8 + t + 4]);
            pa[3] = __float_as_uint(Ks[w * 16 + g + 8][kj * 8 + t + 4]);
            #pragma unroll
            for (int n = 0; n < 8; n++) {
                unsigned vb[2] = { __float_as_uint(Vs[kj * 8 + t    ][n * 8 + g]),
                                   __float_as_uint(Vs[kj * 8 + t + 4][n * 8 + g]) };
                mma_tf32(O[n], pa, vb);
            }
        }
    }

    // ---- epilogue: normalize, write y as [B,T,H*DH]
    const int b = bh >> 4, h = bh & 15;
    const float inv0 = 1.0f / l0, inv1 = 1.0f / l1;
    const int r0 = q0 + w * 16 + g, r1 = r0 + 8;
    #pragma unroll
    for (int n = 0; n < 8; n++) {
        const int col = h * 64 + n * 8 + 2 * t;
        *(float2*)(g_y + ((size_t)b * Tt + r0) * Dd + col) =
            make_float2(O[n][0] * inv0, O[n][1] * inv0);
        *(float2*)(g_y + ((size_t)b * Tt + r1) * Dd + col) =
            make_float2(O[n][2] * inv1, O[n][3] * inv1);
    }
}

// ============================================================================
// 3xTF32 GEMM (NT): C[M,N] = A[M,K] @ B[N,K]^T at ~fp32 accuracy.
// Dekker split: x = hi + lo; x*y ~= hi*hi + hi*lo + lo*hi (3 mmas).
// 128x128 block, 256 threads, 8 warps as 4(m) x 2(n); warp tile 32x64.
// N-bounds guarded (used for N=480/320/1024); M multiple of 128, K of 16.
// ============================================================================
__global__ __launch_bounds__(256) void gemm3_tf32(const float* __restrict__ A,
                                                  const float* __restrict__ Bm,
                                                  float* __restrict__ C,
                                                  int Kn, int Nn)
{
    __shared__ float Ah[128][20], Al[128][20], Bh[128][20], Bl[128][20];

    const int tid  = threadIdx.x;
    const int lane = tid & 31, w = tid >> 5;
    const int g = lane >> 2, t = lane & 3;
    const int wm = w >> 1, wn = w & 1;
    const int mb = blockIdx.y * 128;
    const int nb = blockIdx.x * 128;

    float c[2][8][4];
    #pragma unroll
    for (int mt = 0; mt < 2; mt++)
        #pragma unroll
        for (int n = 0; n < 8; n++)
            c[mt][n][0] = c[mt][n][1] = c[mt][n][2] = c[mt][n][3] = 0.f;

    for (int k0 = 0; k0 < Kn; k0 += 16) {
        #pragma unroll
        for (int i = 0; i < 2; i++) {
            int l = tid + i * 256;
            int r = l >> 2, c4 = (l & 3) << 2;
            float4 av = *(const float4*)(A + (size_t)(mb + r) * Kn + k0 + c4);
            float4 hi, lo;
            hi.x = tf32f(av.x); lo.x = tf32f(av.x - hi.x);
            hi.y = tf32f(av.y); lo.y = tf32f(av.y - hi.y);
            hi.z = tf32f(av.z); lo.z = tf32f(av.z - hi.z);
            hi.w = tf32f(av.w); lo.w = tf32f(av.w - hi.w);
            *(float4*)&Ah[r][c4] = hi;
            *(float4*)&Al[r][c4] = lo;
            float4 bv = make_float4(0.f, 0.f, 0.f, 0.f);
            if (nb + r < Nn)
                bv = *(const float4*)(Bm + (size_t)(nb + r) * Kn + k0 + c4);
            hi.x = tf32f(bv.x); lo.x = tf32f(bv.x - hi.x);
            hi.y = tf32f(bv.y); lo.y = tf32f(bv.y - hi.y);
            hi.z = tf32f(bv.z); lo.z = tf32f(bv.z - hi.z);
            hi.w = tf32f(bv.w); lo.w = tf32f(bv.w - hi.w);
            *(float4*)&Bh[r][c4] = hi;
            *(float4*)&Bl[r][c4] = lo;
        }
        __syncthreads();

        #pragma unroll
        for (int kk = 0; kk < 16; kk += 8) {
            unsigned ah[2][4], al[2][4];
            #pragma unroll
            for (int mt = 0; mt < 2; mt++) {
                const int r = wm * 32 + mt * 16;
                ah[mt][0] = __float_as_uint(Ah[r + g    ][kk + t    ]);
                ah[mt][1] = __float_as_uint(Ah[r + g + 8][kk + t    ]);
                ah[mt][2] = __float_as_uint(Ah[r + g    ][kk + t + 4]);
                ah[mt][3] = __float_as_uint(Ah[r + g + 8][kk + t + 4]);
                al[mt][0] = __float_as_uint(Al[r + g    ][kk + t    ]);
                al[mt][1] = __float_as_uint(Al[r + g + 8][kk + t    ]);
                al[mt][2] = __float_as_uint(Al[r + g    ][kk + t + 4]);
                al[mt][3] = __float_as_uint(Al[r + g + 8][kk + t + 4]);
            }
            #pragma unroll
            for (int n = 0; n < 8; n++) {
                const int rn = wn * 64 + n * 8;
                unsigned bh[2] = { __float_as_uint(Bh[rn + g][kk + t]),
                                   __float_as_uint(Bh[rn + g][kk + t + 4]) };
                unsigned bl[2] = { __float_as_uint(Bl[rn + g][kk + t]),
                                   __float_as_uint(Bl[rn + g][kk + t + 4]) };
                #pragma unroll
                for (int mt = 0; mt < 2; mt++) {
                    mma_tf32(c[mt][n], ah[mt], bh);   // hi*hi
                    mma_tf32(c[mt][n], al[mt], bh);   // lo*hi
                    mma_tf32(c[mt][n], ah[mt], bl);   // hi*lo
                }
            }
        }
        __syncthreads();
    }

    #pragma unroll
    for (int mt = 0; mt < 2; mt++) {
        const int row = mb + wm * 32 + mt * 16 + g;
        #pragma unroll
        for (int n = 0; n < 8; n++) {
            const int col = nb + wn * 64 + n * 8 + 2 * t;
            if (col + 1 < Nn) {
                *(float2*)(C + (size_t)row * Nn + col) =
                    make_float2(c[mt][n][0], c[mt][n][1]);
                *(float2*)(C + (size_t)(row + 8) * Nn + col) =
                    make_float2(c[mt][n][2], c[mt][n][3]);
            } else if (col < Nn) {
                C[(size_t)row * Nn + col]       = c[mt][n][0];
                C[(size_t)(row + 8) * Nn + col] = c[mt][n][2];
            }
        }
    }
}

// ============================================================================
// launch
// ============================================================================
extern "C" void kernel_launch(void* const* d_in, const int* in_sizes, int n_in,
                              void* d_out, int out_size)
{
    const float* x      = (const float*)d_in[0];   // [B,T,D]
    const float* W_abq  = (const float*)d_in[1];   // [480,1024]
    const float* W_abkv = (const float*)d_in[2];   // [320,1024]
    const float* W_o    = (const float*)d_in[3];   // [1024,1024]
    float* out = (float*)d_out;                    // [B,T,D]

    float *abq, *abkv, *yb;
    cudaGetSymbolAddress((void**)&abq,  g_abq);
    cudaGetSymbolAddress((void**)&abkv, g_abkv);
    cudaGetSymbolAddress((void**)&yb,   g_y);

    {   // x @ W_abq^T  -> abq [4096,480]  (3xTF32)
        dim3 grid((NQ + 127) / 128, M / 128);
        gemm3_tf32<<<grid, 256>>>(x, W_abq, abq, Dd, NQ);
    }
    {   // x @ W_abkv^T -> abkv [4096,320]  (3xTF32)
        dim3 grid((NKV + 127) / 128, M / 128);
        gemm3_tf32<<<grid, 256>>>(x, W_abkv, abkv, Dd, NKV);
    }
    build_qkv<<<M, 128>>>();
    {   // TF32 tensor-core flash attention
        dim3 grid(Bb * NH, Tt / 64);
        attn_mma<<<grid, 128>>>();
    }
    {   // y @ W_o^T -> out [4096,1024]  (3xTF32, ~fp32 accuracy)
        dim3 grid(Dd / 128, M / 128);
        gemm3_tf32<<<grid, 256>>>(yb, W_o, out, Dd, Dd);
    }
}

// round 14
// speedup vs baseline: 3.4312x; 1.4505x over previous
#include <cuda_runtime.h>
#include <cuda_bf16.h>
#include <math.h>

// ---------------- problem constants ----------------
namespace {
constexpr int Bb = 2, Tt = 2048, Dd = 1024;
constexpr int NH = 16, DH = 64, CH = 80;
constexpr int RQ = 6, RK = 2, RV = 2;
constexpr int M  = Bb * Tt;            // 4096 rows
constexpr int NQ = RQ * CH;            // 480
constexpr int NKV = (RK + RV) * CH;    // 320
}

// ---------------- scratch (device globals; no cudaMalloc allowed) ----------------
__device__ __align__(16) float g_abq [M * NQ];
__device__ __align__(16) float g_abkv[M * NKV];
__device__ __align__(16) float g_q[Bb * NH * Tt * DH];
__device__ __align__(16) float g_k[Bb * NH * Tt * DH];
__device__ __align__(16) float g_v[Bb * NH * Tt * DH];
__device__ __align__(16) float g_y[M * Dd];

// ---------------- tf32 helpers (attention) ----------------
__device__ __forceinline__ unsigned tf32u(float x) {
    unsigned u;
    asm("cvt.rna.tf32.f32 %0, %1;" : "=r"(u) : "f"(x));
    return u;
}
__device__ __forceinline__ float tf32f(float x) { return __uint_as_float(tf32u(x)); }

// D += A(16x8) * B(8x8), tf32 in, fp32 accumulate
__device__ __forceinline__ void mma_tf32(float c[4], const unsigned a[4], const unsigned b[2]) {
    asm volatile(
        "mma.sync.aligned.m16n8k8.row.col.f32.tf32.tf32.f32 "
        "{%0,%1,%2,%3},{%4,%5,%6,%7},{%8,%9},{%0,%1,%2,%3};"
        : "+f"(c[0]), "+f"(c[1]), "+f"(c[2]), "+f"(c[3])
        : "r"(a[0]), "r"(a[1]), "r"(a[2]), "r"(a[3]), "r"(b[0]), "r"(b[1]));
}

// ---------------- bf16 helpers (GEMMs) ----------------
__device__ __forceinline__ unsigned pack_bf16x2(float a, float b) {
    __nv_bfloat162 h = __floats2bfloat162_rn(a, b);
    return *reinterpret_cast<unsigned*>(&h);
}

// D += A(16x16) * B(16x8), bf16 in, fp32 accumulate
__device__ __forceinline__ void mma_bf16(float c[4], const unsigned a[4], const unsigned b[2]) {
    asm volatile(
        "mma.sync.aligned.m16n8k16.row.col.f32.bf16.bf16.f32 "
        "{%0,%1,%2,%3},{%4,%5,%6,%7},{%8,%9},{%0,%1,%2,%3};"
        : "+f"(c[0]), "+f"(c[1]), "+f"(c[2]), "+f"(c[3])
        : "r"(a[0]), "r"(a[1]), "r"(a[2]), "r"(a[3]), "r"(b[0]), "r"(b[1]));
}

// ============================================================================
// build_qkv: RoPE + rank contraction
// ============================================================================
__global__ __launch_bounds__(128) void build_qkv()
{
    const int bt = blockIdx.x;
    const int b = bt / Tt, t = bt % Tt;
    const int tid = threadIdx.x;

    __shared__ float sq [NQ];
    __shared__ float skv[NKV];

    for (int i = tid; i < NQ;  i += 128) sq[i]  = g_abq [(size_t)bt * NQ  + i];
    for (int i = tid; i < NKV; i += 128) skv[i] = g_abkv[(size_t)bt * NKV + i];
    __syncthreads();

    {
        const int rr = tid >> 5, d = tid & 31;
        const float inv = __expf(-(float)d * (9.2103403719761836f / 32.0f));
        const float fr  = (float)t * inv;
        const float c = cosf(fr), s = sinf(fr);
        const int base = rr * CH + NH;
        const float x1 = skv[base + d];
        const float x2 = skv[base + 32 + d];
        skv[base + d]      =  x1 * c + x2 * s;
        skv[base + 32 + d] = -x1 * s + x2 * c;
    }
    __syncthreads();

    for (int o = tid; o < NH * DH; o += 128) {
        const int h = o >> 6, dd = o & 63;
        float acc = 0.f;
        #pragma unroll
        for (int r = 0; r < RQ; r++)
            acc = fmaf(sq[r * CH + h], sq[r * CH + NH + dd], acc);
        g_q[(((size_t)(b * NH + h)) * Tt + t) * DH + dd] = acc * (1.0f / RQ);
    }
    for (int o = tid; o < NH * DH; o += 128) {
        const int h = o >> 6, dd = o & 63;
        float ak = fmaf(skv[0 * CH + h], skv[0 * CH + NH + dd],
                        skv[1 * CH + h] * skv[1 * CH + NH + dd]);
        float av = fmaf(skv[2 * CH + h], skv[2 * CH + NH + dd],
                        skv[3 * CH + h] * skv[3 * CH + NH + dd]);
        const size_t idx = (((size_t)(b * NH + h)) * Tt + t) * DH + dd;
        g_k[idx] = ak * 0.5f;
        g_v[idx] = av * 0.5f;
    }
}

// ============================================================================
// Causal flash attention with TF32 mma.sync (m16n8k8), fp32 accumulate.
// (UNCHANGED from the 546.8us passing kernel.)
// ============================================================================
__global__ __launch_bounds__(128) void attn_mma()
{
    __shared__ float Ks[64][68];   // K tile [kcol][d]; later P [w*16+row][j]
    __shared__ float Vs[64][72];   // V tile [j][d]

    const int tid  = threadIdx.x;
    const int lane = tid & 31;
    const int w    = tid >> 5;
    const int g    = lane >> 2;    // group id (row within fragment)
    const int t    = lane & 3;     // thread-in-group (col within fragment)
    const int bh   = blockIdx.x;
    const int qt   = ((int)gridDim.y - 1) - (int)blockIdx.y;  // longest first
    const int q0   = qt * 64;

    const float* qp = g_q + (size_t)bh * Tt * DH;
    const float* kp = g_k + (size_t)bh * Tt * DH;
    const float* vp = g_v + (size_t)bh * Tt * DH;

    // ---- stage Q (pre-scaled by 1/sqrt(DH)) into Ks, pull fragments to regs
    #pragma unroll
    for (int i = 0; i < 8; i++) {
        int l = tid + i * 128;
        int r = l >> 4, d4 = (l & 15) << 2;
        float4 qv = *(const float4*)(qp + (size_t)(q0 + r) * DH + d4);
        Ks[r][d4 + 0] = tf32f(qv.x * 0.125f);
        Ks[r][d4 + 1] = tf32f(qv.y * 0.125f);
        Ks[r][d4 + 2] = tf32f(qv.z * 0.125f);
        Ks[r][d4 + 3] = tf32f(qv.w * 0.125f);
    }
    __syncthreads();
    unsigned Qa[8][4];
    #pragma unroll
    for (int dk = 0; dk < 8; dk++) {
        Qa[dk][0] = __float_as_uint(Ks[w * 16 + g    ][dk * 8 + t    ]);
        Qa[dk][1] = __float_as_uint(Ks[w * 16 + g + 8][dk * 8 + t    ]);
        Qa[dk][2] = __float_as_uint(Ks[w * 16 + g    ][dk * 8 + t + 4]);
        Qa[dk][3] = __float_as_uint(Ks[w * 16 + g + 8][dk * 8 + t + 4]);
    }

    float O[8][4];
    #pragma unroll
    for (int n = 0; n < 8; n++) { O[n][0] = O[n][1] = O[n][2] = O[n][3] = 0.f; }
    float m0 = -1e30f, m1 = -1e30f, l0 = 0.f, l1 = 0.f;

    for (int kt = 0; kt <= qt; kt++) {
        const int k0 = kt * 64;
        __syncthreads();
        #pragma unroll
        for (int i = 0; i < 8; i++) {
            int l = tid + i * 128;
            int r = l >> 4, d4 = (l & 15) << 2;
            float4 kv = *(const float4*)(kp + (size_t)(k0 + r) * DH + d4);
            Ks[r][d4 + 0] = tf32f(kv.x);
            Ks[r][d4 + 1] = tf32f(kv.y);
            Ks[r][d4 + 2] = tf32f(kv.z);
            Ks[r][d4 + 3] = tf32f(kv.w);
            float4 vv = *(const float4*)(vp + (size_t)(k0 + r) * DH + d4);
            Vs[r][d4 + 0] = tf32f(vv.x);
            Vs[r][d4 + 1] = tf32f(vv.y);
            Vs[r][d4 + 2] = tf32f(vv.z);
            Vs[r][d4 + 3] = tf32f(vv.w);
        }
        __syncthreads();

        // ---- S = Q K^T
        float c[8][4];
        #pragma unroll
        for (int n = 0; n < 8; n++) { c[n][0] = c[n][1] = c[n][2] = c[n][3] = 0.f; }
        #pragma unroll
        for (int dk = 0; dk < 8; dk++) {
            #pragma unroll
            for (int n = 0; n < 8; n++) {
                unsigned bb[2] = { __float_as_uint(Ks[n * 8 + g][dk * 8 + t]),
                                   __float_as_uint(Ks[n * 8 + g][dk * 8 + t + 4]) };
                mma_tf32(c[n], Qa[dk], bb);
            }
        }

        if (kt == qt) {   // causal mask on diagonal tile
            const int r0 = w * 16 + g, r1 = r0 + 8;
            #pragma unroll
            for (int n = 0; n < 8; n++) {
                const int cb = n * 8 + 2 * t;
                if (cb     > r0) c[n][0] = -1e30f;
                if (cb + 1 > r0) c[n][1] = -1e30f;
                if (cb     > r1) c[n][2] = -1e30f;
                if (cb + 1 > r1) c[n][3] = -1e30f;
            }
        }

        // ---- online softmax (rows g and g+8; 4-lane row groups)
        float tm0 = -1e30f, tm1 = -1e30f;
        #pragma unroll
        for (int n = 0; n < 8; n++) {
            tm0 = fmaxf(tm0, fmaxf(c[n][0], c[n][1]));
            tm1 = fmaxf(tm1, fmaxf(c[n][2], c[n][3]));
        }
        #pragma unroll
        for (int o = 1; o < 4; o <<= 1) {
            tm0 = fmaxf(tm0, __shfl_xor_sync(0xffffffffu, tm0, o));
            tm1 = fmaxf(tm1, __shfl_xor_sync(0xffffffffu, tm1, o));
        }
        const float mn0 = fmaxf(m0, tm0), mn1 = fmaxf(m1, tm1);
        const float al0 = __expf(m0 - mn0), al1 = __expf(m1 - mn1);
        m0 = mn0; m1 = mn1;
        float tl0 = 0.f, tl1 = 0.f;
        #pragma unroll
        for (int n = 0; n < 8; n++) {
            c[n][0] = __expf(c[n][0] - mn0);  tl0 += c[n][0];
            c[n][1] = __expf(c[n][1] - mn0);  tl0 += c[n][1];
            c[n][2] = __expf(c[n][2] - mn1);  tl1 += c[n][2];
            c[n][3] = __expf(c[n][3] - mn1);  tl1 += c[n][3];
        }
        #pragma unroll
        for (int o = 1; o < 4; o <<= 1) {
            tl0 += __shfl_xor_sync(0xffffffffu, tl0, o);
            tl1 += __shfl_xor_sync(0xffffffffu, tl1, o);
        }
        l0 = l0 * al0 + tl0;
        l1 = l1 * al1 + tl1;
        #pragma unroll
        for (int n = 0; n < 8; n++) {
            O[n][0] *= al0; O[n][1] *= al0;
            O[n][2] *= al1; O[n][3] *= al1;
        }

        __syncthreads();
        #pragma unroll
        for (int n = 0; n < 8; n++) {
            *(float2*)&Ks[w * 16 + g    ][n * 8 + 2 * t] =
                make_float2(tf32f(c[n][0]), tf32f(c[n][1]));
            *(float2*)&Ks[w * 16 + g + 8][n * 8 + 2 * t] =
                make_float2(tf32f(c[n][2]), tf32f(c[n][3]));
        }
        __syncwarp();

        // ---- O += P V
        #pragma unroll
        for (int kj = 0; kj < 8; kj++) {
            unsigned pa[4];
            pa[0] = __float_as_uint(Ks[w * 16 + g    ][kj * 8 + t    ]);
            pa[1] = __float_as_uint(Ks[w * 16 + g + 8][kj * 8 + t    ]);
            pa[2] = __float_as_uint(Ks[w * 16 + g    ][kj * 8 + t + 4]);
            pa[3] = __float_as_uint(Ks[w * 16 + g + 8][kj * 8 + t + 4]);
            #pragma unroll
            for (int n = 0; n < 8; n++) {
                unsigned vb[2] = { __float_as_uint(Vs[kj * 8 + t    ][n * 8 + g]),
                                   __float_as_uint(Vs[kj * 8 + t + 4][n * 8 + g]) };
                mma_tf32(O[n], pa, vb);
            }
        }
    }

    // ---- epilogue
    const int b = bh >> 4, h = bh & 15;
    const float inv0 = 1.0f / l0, inv1 = 1.0f / l1;
    const int r0 = q0 + w * 16 + g, r1 = r0 + 8;
    #pragma unroll
    for (int n = 0; n < 8; n++) {
        const int col = h * 64 + n * 8 + 2 * t;
        *(float2*)(g_y + ((size_t)b * Tt + r0) * Dd + col) =
            make_float2(O[n][0] * inv0, O[n][1] * inv0);
        *(float2*)(g_y + ((size_t)b * Tt + r1) * Dd + col) =
            make_float2(O[n][2] * inv1, O[n][3] * inv1);
    }
}

// ============================================================================
// 3x bf16-split GEMM core (NT): C[M,N] = A[M,K] @ B[N,K]^T.
// x = hi + lo (bf16 each); x*y ~= hi*hi + lo*hi + hi*lo  (err ~ eps_bf16^2).
// mma.m16n8k16.bf16: same cycle cost as tf32 k8 but 2x k-depth -> 2x faster
// than 3xTF32. 128x128 block tile, BK=32, 256 threads, 8 warps (4m x 2n),
// warp tile 32x64. Smem rows stride 20 words -> conflict-free frag reads.
// ============================================================================
__device__ __forceinline__ void gemm3_core(const float* __restrict__ A,
                                           const float* __restrict__ Bm,
                                           float* __restrict__ C,
                                           int Kn, int Nn, int mb, int nb)
{
    __shared__ unsigned Ah[128][20], Al[128][20], Bh[128][20], Bl[128][20];

    const int tid  = threadIdx.x;
    const int lane = tid & 31, w = tid >> 5;
    const int g = lane >> 2, t = lane & 3;
    const int wm = w >> 1, wn = w & 1;

    float c[2][8][4];
    #pragma unroll
    for (int mt = 0; mt < 2; mt++)
        #pragma unroll
        for (int n = 0; n < 8; n++)
            c[mt][n][0] = c[mt][n][1] = c[mt][n][2] = c[mt][n][3] = 0.f;

    for (int k0 = 0; k0 < Kn; k0 += 32) {
        // ---- stage tiles: 128 rows x 32 k-floats as bf16 hi/lo pairs
        #pragma unroll
        for (int i = 0; i < 4; i++) {
            int l = tid + i * 256;
            int r = l >> 3, c8 = l & 7;           // c8: float4 index in row
            float4 av = *(const float4*)(A + (size_t)(mb + r) * Kn + k0 + c8 * 4);
            float hx = __bfloat162float(__float2bfloat16_rn(av.x));
            float hy = __bfloat162float(__float2bfloat16_rn(av.y));
            float hz = __bfloat162float(__float2bfloat16_rn(av.z));
            float hw = __bfloat162float(__float2bfloat16_rn(av.w));
            Ah[r][c8 * 2 + 0] = pack_bf16x2(hx, hy);
            Ah[r][c8 * 2 + 1] = pack_bf16x2(hz, hw);
            Al[r][c8 * 2 + 0] = pack_bf16x2(av.x - hx, av.y - hy);
            Al[r][c8 * 2 + 1] = pack_bf16x2(av.z - hz, av.w - hw);

            float4 bv = make_float4(0.f, 0.f, 0.f, 0.f);
            if (nb + r < Nn)
                bv = *(const float4*)(Bm + (size_t)(nb + r) * Kn + k0 + c8 * 4);
            hx = __bfloat162float(__float2bfloat16_rn(bv.x));
            hy = __bfloat162float(__float2bfloat16_rn(bv.y));
            hz = __bfloat162float(__float2bfloat16_rn(bv.z));
            hw = __bfloat162float(__float2bfloat16_rn(bv.w));
            Bh[r][c8 * 2 + 0] = pack_bf16x2(hx, hy);
            Bh[r][c8 * 2 + 1] = pack_bf16x2(hz, hw);
            Bl[r][c8 * 2 + 0] = pack_bf16x2(bv.x - hx, bv.y - hy);
            Bl[r][c8 * 2 + 1] = pack_bf16x2(bv.z - hz, bv.w - hw);
        }
        __syncthreads();

        // ---- 2 k16-steps per BK=32
        #pragma unroll
        for (int ks = 0; ks < 2; ks++) {
            const int kb = ks * 8;
            unsigned ah[2][4], al[2][4];
            #pragma unroll
            for (int mt = 0; mt < 2; mt++) {
                const int r = wm * 32 + mt * 16;
                ah[mt][0] = Ah[r + g    ][kb + t    ];
                ah[mt][1] = Ah[r + g + 8][kb + t    ];
                ah[mt][2] = Ah[r + g    ][kb + t + 4];
                ah[mt][3] = Ah[r + g + 8][kb + t + 4];
                al[mt][0] = Al[r + g    ][kb + t    ];
                al[mt][1] = Al[r + g + 8][kb + t    ];
                al[mt][2] = Al[r + g    ][kb + t + 4];
                al[mt][3] = Al[r + g + 8][kb + t + 4];
            }
            #pragma unroll
            for (int n = 0; n < 8; n++) {
                const int rn = wn * 64 + n * 8;
                unsigned bh[2] = { Bh[rn + g][kb + t], Bh[rn + g][kb + t + 4] };
                unsigned bl[2] = { Bl[rn + g][kb + t], Bl[rn + g][kb + t + 4] };
                #pragma unroll
                for (int mt = 0; mt < 2; mt++) {
                    mma_bf16(c[mt][n], ah[mt], bh);   // hi*hi
                    mma_bf16(c[mt][n], al[mt], bh);   // lo*hi
                    mma_bf16(c[mt][n], ah[mt], bl);   // hi*lo
                }
            }
        }
        __syncthreads();
    }

    #pragma unroll
    for (int mt = 0; mt < 2; mt++) {
        const int row = mb + wm * 32 + mt * 16 + g;
        #pragma unroll
        for (int n = 0; n < 8; n++) {
            const int col = nb + wn * 64 + n * 8 + 2 * t;
            if (col + 1 < Nn) {
                *(float2*)(C + (size_t)row * Nn + col) =
                    make_float2(c[mt][n][0], c[mt][n][1]);
                *(float2*)(C + (size_t)(row + 8) * Nn + col) =
                    make_float2(c[mt][n][2], c[mt][n][3]);
            } else if (col < Nn) {
                C[(size_t)row * Nn + col]       = c[mt][n][0];
                C[(size_t)(row + 8) * Nn + col] = c[mt][n][2];
            }
        }
    }
}

// W_o GEMM: grid (N/128, M/128)
__global__ __launch_bounds__(256) void gemm3_bf16(const float* __restrict__ A,
                                                  const float* __restrict__ Bm,
                                                  float* __restrict__ C,
                                                  int Kn, int Nn)
{
    gemm3_core(A, Bm, C, Kn, Nn, blockIdx.y * 128, blockIdx.x * 128);
}

// Fused projections: grid.x = 4 (abq n-tiles) + 3 (abkv n-tiles) = 7, grid.y = 32
__global__ __launch_bounds__(256) void proj_fused(const float* __restrict__ x,
                                                  const float* __restrict__ W_abq,
                                                  const float* __restrict__ W_abkv,
                                                  float* __restrict__ abq,
                                                  float* __restrict__ abkv)
{
    const int bx = blockIdx.x;
    if (bx < 4)
        gemm3_core(x, W_abq,  abq,  Dd, NQ,  blockIdx.y * 128, bx * 128);
    else
        gemm3_core(x, W_abkv, abkv, Dd, NKV, blockIdx.y * 128, (bx - 4) * 128);
}

// ============================================================================
// launch
// ============================================================================
extern "C" void kernel_launch(void* const* d_in, const int* in_sizes, int n_in,
                              void* d_out, int out_size)
{
    const float* x      = (const float*)d_in[0];   // [B,T,D]
    const float* W_abq  = (const float*)d_in[1];   // [480,1024]
    const float* W_abkv = (const float*)d_in[2];   // [320,1024]
    const float* W_o    = (const float*)d_in[3];   // [1024,1024]
    float* out = (float*)d_out;                    // [B,T,D]

    float *abq, *abkv, *yb;
    cudaGetSymbolAddress((void**)&abq,  g_abq);
    cudaGetSymbolAddress((void**)&abkv, g_abkv);
    cudaGetSymbolAddress((void**)&yb,   g_y);

    {   // fused x@W_abq^T and x@W_abkv^T  (3x bf16-split)
        dim3 grid(7, M / 128);
        proj_fused<<<grid, 256>>>(x, W_abq, W_abkv, abq, abkv);
    }
    build_qkv<<<M, 128>>>();
    {   // TF32 tensor-core flash attention (unchanged)
        dim3 grid(Bb * NH, Tt / 64);
        attn_mma<<<grid, 128>>>();
    }
    {   // y @ W_o^T -> out  (3x bf16-split)
        dim3 grid(Dd / 128, M / 128);
        gemm3_bf16<<<grid, 256>>>(yb, W_o, out, Dd, Dd);
    }
}

// round 17
// speedup vs baseline: 3.6926x; 1.0762x over previous
#include <cuda_runtime.h>
#include <cuda_bf16.h>
#include <math.h>

// ---------------- problem constants ----------------
namespace {
constexpr int Bb = 2, Tt = 2048, Dd = 1024;
constexpr int NH = 16, DH = 64, CH = 80;
constexpr int RQ = 6, RK = 2, RV = 2;
constexpr int M  = Bb * Tt;            // 4096 rows
constexpr int NQ = RQ * CH;            // 480
constexpr int NKV = (RK + RV) * CH;    // 320
}

// ---------------- scratch (device globals; no cudaMalloc allowed) ----------------
__device__ __align__(16) float g_abq [M * NQ];
__device__ __align__(16) float g_abkv[M * NKV];
__device__ __align__(16) float g_q[Bb * NH * Tt * DH];
__device__ __align__(16) float g_k[Bb * NH * Tt * DH];
__device__ __align__(16) float g_v[Bb * NH * Tt * DH];
__device__ __align__(16) float g_y[M * Dd];

// ---------------- tf32 helpers (attention) ----------------
__device__ __forceinline__ unsigned tf32u(float x) {
    unsigned u;
    asm("cvt.rna.tf32.f32 %0, %1;" : "=r"(u) : "f"(x));
    return u;
}
__device__ __forceinline__ float tf32f(float x) { return __uint_as_float(tf32u(x)); }

// D += A(16x8) * B(8x8), tf32 in, fp32 accumulate
__device__ __forceinline__ void mma_tf32(float c[4], const unsigned a[4], const unsigned b[2]) {
    asm volatile(
        "mma.sync.aligned.m16n8k8.row.col.f32.tf32.tf32.f32 "
        "{%0,%1,%2,%3},{%4,%5,%6,%7},{%8,%9},{%0,%1,%2,%3};"
        : "+f"(c[0]), "+f"(c[1]), "+f"(c[2]), "+f"(c[3])
        : "r"(a[0]), "r"(a[1]), "r"(a[2]), "r"(a[3]), "r"(b[0]), "r"(b[1]));
}

// ---------------- bf16 helpers (GEMMs) ----------------
__device__ __forceinline__ unsigned pack_bf16x2(float a, float b) {
    __nv_bfloat162 h = __floats2bfloat162_rn(a, b);
    return *reinterpret_cast<unsigned*>(&h);
}

// D += A(16x16) * B(16x8), bf16 in, fp32 accumulate
__device__ __forceinline__ void mma_bf16(float c[4], const unsigned a[4], const unsigned b[2]) {
    asm volatile(
        "mma.sync.aligned.m16n8k16.row.col.f32.bf16.bf16.f32 "
        "{%0,%1,%2,%3},{%4,%5,%6,%7},{%8,%9},{%0,%1,%2,%3};"
        : "+f"(c[0]), "+f"(c[1]), "+f"(c[2]), "+f"(c[3])
        : "r"(a[0]), "r"(a[1]), "r"(a[2]), "r"(a[3]), "r"(b[0]), "r"(b[1]));
}

// ============================================================================
// build_qkv: RoPE + rank contraction
// ============================================================================
__global__ __launch_bounds__(128) void build_qkv()
{
    const int bt = blockIdx.x;
    const int b = bt / Tt, t = bt % Tt;
    const int tid = threadIdx.x;

    __shared__ float sq [NQ];
    __shared__ float skv[NKV];

    for (int i = tid; i < NQ;  i += 128) sq[i]  = g_abq [(size_t)bt * NQ  + i];
    for (int i = tid; i < NKV; i += 128) skv[i] = g_abkv[(size_t)bt * NKV + i];
    __syncthreads();

    {
        const int rr = tid >> 5, d = tid & 31;
        const float inv = __expf(-(float)d * (9.2103403719761836f / 32.0f));
        const float fr  = (float)t * inv;
        const float c = cosf(fr), s = sinf(fr);
        const int base = rr * CH + NH;
        const float x1 = skv[base + d];
        const float x2 = skv[base + 32 + d];
        skv[base + d]      =  x1 * c + x2 * s;
        skv[base + 32 + d] = -x1 * s + x2 * c;
    }
    __syncthreads();

    for (int o = tid; o < NH * DH; o += 128) {
        const int h = o >> 6, dd = o & 63;
        float acc = 0.f;
        #pragma unroll
        for (int r = 0; r < RQ; r++)
            acc = fmaf(sq[r * CH + h], sq[r * CH + NH + dd], acc);
        g_q[(((size_t)(b * NH + h)) * Tt + t) * DH + dd] = acc * (1.0f / RQ);
    }
    for (int o = tid; o < NH * DH; o += 128) {
        const int h = o >> 6, dd = o & 63;
        float ak = fmaf(skv[0 * CH + h], skv[0 * CH + NH + dd],
                        skv[1 * CH + h] * skv[1 * CH + NH + dd]);
        float av = fmaf(skv[2 * CH + h], skv[2 * CH + NH + dd],
                        skv[3 * CH + h] * skv[3 * CH + NH + dd]);
        const size_t idx = (((size_t)(b * NH + h)) * Tt + t) * DH + dd;
        g_k[idx] = ak * 0.5f;
        g_v[idx] = av * 0.5f;
    }
}

// ============================================================================
// Causal flash attention with TF32 mma.sync (m16n8k8), fp32 accumulate.
// (UNCHANGED from the passing 377us kernel.)
// ============================================================================
__global__ __launch_bounds__(128) void attn_mma()
{
    __shared__ float Ks[64][68];   // K tile [kcol][d]; later P [w*16+row][j]
    __shared__ float Vs[64][72];   // V tile [j][d]

    const int tid  = threadIdx.x;
    const int lane = tid & 31;
    const int w    = tid >> 5;
    const int g    = lane >> 2;    // group id (row within fragment)
    const int t    = lane & 3;     // thread-in-group (col within fragment)
    const int bh   = blockIdx.x;
    const int qt   = ((int)gridDim.y - 1) - (int)blockIdx.y;  // longest first
    const int q0   = qt * 64;

    const float* qp = g_q + (size_t)bh * Tt * DH;
    const float* kp = g_k + (size_t)bh * Tt * DH;
    const float* vp = g_v + (size_t)bh * Tt * DH;

    // ---- stage Q (pre-scaled by 1/sqrt(DH)) into Ks, pull fragments to regs
    #pragma unroll
    for (int i = 0; i < 8; i++) {
        int l = tid + i * 128;
        int r = l >> 4, d4 = (l & 15) << 2;
        float4 qv = *(const float4*)(qp + (size_t)(q0 + r) * DH + d4);
        Ks[r][d4 + 0] = tf32f(qv.x * 0.125f);
        Ks[r][d4 + 1] = tf32f(qv.y * 0.125f);
        Ks[r][d4 + 2] = tf32f(qv.z * 0.125f);
        Ks[r][d4 + 3] = tf32f(qv.w * 0.125f);
    }
    __syncthreads();
    unsigned Qa[8][4];
    #pragma unroll
    for (int dk = 0; dk < 8; dk++) {
        Qa[dk][0] = __float_as_uint(Ks[w * 16 + g    ][dk * 8 + t    ]);
        Qa[dk][1] = __float_as_uint(Ks[w * 16 + g + 8][dk * 8 + t    ]);
        Qa[dk][2] = __float_as_uint(Ks[w * 16 + g    ][dk * 8 + t + 4]);
        Qa[dk][3] = __float_as_uint(Ks[w * 16 + g + 8][dk * 8 + t + 4]);
    }

    float O[8][4];
    #pragma unroll
    for (int n = 0; n < 8; n++) { O[n][0] = O[n][1] = O[n][2] = O[n][3] = 0.f; }
    float m0 = -1e30f, m1 = -1e30f, l0 = 0.f, l1 = 0.f;

    for (int kt = 0; kt <= qt; kt++) {
        const int k0 = kt * 64;
        __syncthreads();
        #pragma unroll
        for (int i = 0; i < 8; i++) {
            int l = tid + i * 128;
            int r = l >> 4, d4 = (l & 15) << 2;
            float4 kv = *(const float4*)(kp + (size_t)(k0 + r) * DH + d4);
            Ks[r][d4 + 0] = tf32f(kv.x);
            Ks[r][d4 + 1] = tf32f(kv.y);
            Ks[r][d4 + 2] = tf32f(kv.z);
            Ks[r][d4 + 3] = tf32f(kv.w);
            float4 vv = *(const float4*)(vp + (size_t)(k0 + r) * DH + d4);
            Vs[r][d4 + 0] = tf32f(vv.x);
            Vs[r][d4 + 1] = tf32f(vv.y);
            Vs[r][d4 + 2] = tf32f(vv.z);
            Vs[r][d4 + 3] = tf32f(vv.w);
        }
        __syncthreads();

        // ---- S = Q K^T
        float c[8][4];
        #pragma unroll
        for (int n = 0; n < 8; n++) { c[n][0] = c[n][1] = c[n][2] = c[n][3] = 0.f; }
        #pragma unroll
        for (int dk = 0; dk < 8; dk++) {
            #pragma unroll
            for (int n = 0; n < 8; n++) {
                unsigned bb[2] = { __float_as_uint(Ks[n * 8 + g][dk * 8 + t]),
                                   __float_as_uint(Ks[n * 8 + g][dk * 8 + t + 4]) };
                mma_tf32(c[n], Qa[dk], bb);
            }
        }

        if (kt == qt) {   // causal mask on diagonal tile
            const int r0 = w * 16 + g, r1 = r0 + 8;
            #pragma unroll
            for (int n = 0; n < 8; n++) {
                const int cb = n * 8 + 2 * t;
                if (cb     > r0) c[n][0] = -1e30f;
                if (cb + 1 > r0) c[n][1] = -1e30f;
                if (cb     > r1) c[n][2] = -1e30f;
                if (cb + 1 > r1) c[n][3] = -1e30f;
            }
        }

        // ---- online softmax (rows g and g+8; 4-lane row groups)
        float tm0 = -1e30f, tm1 = -1e30f;
        #pragma unroll
        for (int n = 0; n < 8; n++) {
            tm0 = fmaxf(tm0, fmaxf(c[n][0], c[n][1]));
            tm1 = fmaxf(tm1, fmaxf(c[n][2], c[n][3]));
        }
        #pragma unroll
        for (int o = 1; o < 4; o <<= 1) {
            tm0 = fmaxf(tm0, __shfl_xor_sync(0xffffffffu, tm0, o));
            tm1 = fmaxf(tm1, __shfl_xor_sync(0xffffffffu, tm1, o));
        }
        const float mn0 = fmaxf(m0, tm0), mn1 = fmaxf(m1, tm1);
        const float al0 = __expf(m0 - mn0), al1 = __expf(m1 - mn1);
        m0 = mn0; m1 = mn1;
        float tl0 = 0.f, tl1 = 0.f;
        #pragma unroll
        for (int n = 0; n < 8; n++) {
            c[n][0] = __expf(c[n][0] - mn0);  tl0 += c[n][0];
            c[n][1] = __expf(c[n][1] - mn0);  tl0 += c[n][1];
            c[n][2] = __expf(c[n][2] - mn1);  tl1 += c[n][2];
            c[n][3] = __expf(c[n][3] - mn1);  tl1 += c[n][3];
        }
        #pragma unroll
        for (int o = 1; o < 4; o <<= 1) {
            tl0 += __shfl_xor_sync(0xffffffffu, tl0, o);
            tl1 += __shfl_xor_sync(0xffffffffu, tl1, o);
        }
        l0 = l0 * al0 + tl0;
        l1 = l1 * al1 + tl1;
        #pragma unroll
        for (int n = 0; n < 8; n++) {
            O[n][0] *= al0; O[n][1] *= al0;
            O[n][2] *= al1; O[n][3] *= al1;
        }

        __syncthreads();
        #pragma unroll
        for (int n = 0; n < 8; n++) {
            *(float2*)&Ks[w * 16 + g    ][n * 8 + 2 * t] =
                make_float2(tf32f(c[n][0]), tf32f(c[n][1]));
            *(float2*)&Ks[w * 16 + g + 8][n * 8 + 2 * t] =
                make_float2(tf32f(c[n][2]), tf32f(c[n][3]));
        }
        __syncwarp();

        // ---- O += P V
        #pragma unroll
        for (int kj = 0; kj < 8; kj++) {
            unsigned pa[4];
            pa[0] = __float_as_uint(Ks[w * 16 + g    ][kj * 8 + t    ]);
            pa[1] = __float_as_uint(Ks[w * 16 + g + 8][kj * 8 + t    ]);
            pa[2] = __float_as_uint(Ks[w * 16 + g    ][kj * 8 + t + 4]);
            pa[3] = __float_as_uint(Ks[w * 16 + g + 8][kj * 8 + t + 4]);
            #pragma unroll
            for (int n = 0; n < 8; n++) {
                unsigned vb[2] = { __float_as_uint(Vs[kj * 8 + t    ][n * 8 + g]),
                                   __float_as_uint(Vs[kj * 8 + t + 4][n * 8 + g]) };
                mma_tf32(O[n], pa, vb);
            }
        }
    }

    // ---- epilogue
    const int b = bh >> 4, h = bh & 15;
    const float inv0 = 1.0f / l0, inv1 = 1.0f / l1;
    const int r0 = q0 + w * 16 + g, r1 = r0 + 8;
    #pragma unroll
    for (int n = 0; n < 8; n++) {
        const int col = h * 64 + n * 8 + 2 * t;
        *(float2*)(g_y + ((size_t)b * Tt + r0) * Dd + col) =
            make_float2(O[n][0] * inv0, O[n][1] * inv0);
        *(float2*)(g_y + ((size_t)b * Tt + r1) * Dd + col) =
            make_float2(O[n][2] * inv1, O[n][3] * inv1);
    }
}

// ============================================================================
// 3x bf16-split GEMM core (NT): C[M,N] = A[M,K] @ B[N,K]^T.
// x = hi + lo (bf16 each); x*y ~= hi*hi + lo*hi + hi*lo  (err ~ eps_bf16^2).
// 128x128 block tile, BK=32, 256 threads, 8 warps (4m x 2n), warp tile 32x64.
// Callers are compiled with __launch_bounds__(256, 2): <=128 regs so TWO CTAs
// co-reside per SM -> inter-CTA overlap hides the staging/sync phases.
// ============================================================================
__device__ __forceinline__ void gemm3_core(const float* __restrict__ A,
                                           const float* __restrict__ Bm,
                                           float* __restrict__ C,
                                           int Kn, int Nn, int mb, int nb)
{
    __shared__ unsigned Ah[128][20], Al[128][20], Bh[128][20], Bl[128][20];

    const int tid  = threadIdx.x;
    const int lane = tid & 31, w = tid >> 5;
    const int g = lane >> 2, t = lane & 3;
    const int wm = w >> 1, wn = w & 1;

    float c[2][8][4];
    #pragma unroll
    for (int mt = 0; mt < 2; mt++)
        #pragma unroll
        for (int n = 0; n < 8; n++)
            c[mt][n][0] = c[mt][n][1] = c[mt][n][2] = c[mt][n][3] = 0.f;

    for (int k0 = 0; k0 < Kn; k0 += 32) {
        // ---- stage tiles: 128 rows x 32 k-floats as bf16 hi/lo pairs
        #pragma unroll
        for (int i = 0; i < 4; i++) {
            int l = tid + i * 256;
            int r = l >> 3, c8 = l & 7;           // c8: float4 index in row
            float4 av = *(const float4*)(A + (size_t)(mb + r) * Kn + k0 + c8 * 4);
            float hx = __bfloat162float(__float2bfloat16_rn(av.x));
            float hy = __bfloat162float(__float2bfloat16_rn(av.y));
            float hz = __bfloat162float(__float2bfloat16_rn(av.z));
            float hw = __bfloat162float(__float2bfloat16_rn(av.w));
            Ah[r][c8 * 2 + 0] = pack_bf16x2(hx, hy);
            Ah[r][c8 * 2 + 1] = pack_bf16x2(hz, hw);
            Al[r][c8 * 2 + 0] = pack_bf16x2(av.x - hx, av.y - hy);
            Al[r][c8 * 2 + 1] = pack_bf16x2(av.z - hz, av.w - hw);

            float4 bv = make_float4(0.f, 0.f, 0.f, 0.f);
            if (nb + r < Nn)
                bv = *(const float4*)(Bm + (size_t)(nb + r) * Kn + k0 + c8 * 4);
            hx = __bfloat162float(__float2bfloat16_rn(bv.x));
            hy = __bfloat162float(__float2bfloat16_rn(bv.y));
            hz = __bfloat162float(__float2bfloat16_rn(bv.z));
            hw = __bfloat162float(__float2bfloat16_rn(bv.w));
            Bh[r][c8 * 2 + 0] = pack_bf16x2(hx, hy);
            Bh[r][c8 * 2 + 1] = pack_bf16x2(hz, hw);
            Bl[r][c8 * 2 + 0] = pack_bf16x2(bv.x - hx, bv.y - hy);
            Bl[r][c8 * 2 + 1] = pack_bf16x2(bv.z - hz, bv.w - hw);
        }
        __syncthreads();

        // ---- 2 k16-steps per BK=32
        #pragma unroll
        for (int ks = 0; ks < 2; ks++) {
            const int kb = ks * 8;
            unsigned ah[2][4], al[2][4];
            #pragma unroll
            for (int mt = 0; mt < 2; mt++) {
                const int r = wm * 32 + mt * 16;
                ah[mt][0] = Ah[r + g    ][kb + t    ];
                ah[mt][1] = Ah[r + g + 8][kb + t    ];
                ah[mt][2] = Ah[r + g    ][kb + t + 4];
                ah[mt][3] = Ah[r + g + 8][kb + t + 4];
                al[mt][0] = Al[r + g    ][kb + t    ];
                al[mt][1] = Al[r + g + 8][kb + t    ];
                al[mt][2] = Al[r + g    ][kb + t + 4];
                al[mt][3] = Al[r + g + 8][kb + t + 4];
            }
            #pragma unroll
            for (int n = 0; n < 8; n++) {
                const int rn = wn * 64 + n * 8;
                unsigned bh[2] = { Bh[rn + g][kb + t], Bh[rn + g][kb + t + 4] };
                unsigned bl[2] = { Bl[rn + g][kb + t], Bl[rn + g][kb + t + 4] };
                #pragma unroll
                for (int mt = 0; mt < 2; mt++) {
                    mma_bf16(c[mt][n], ah[mt], bh);   // hi*hi
                    mma_bf16(c[mt][n], al[mt], bh);   // lo*hi
                    mma_bf16(c[mt][n], ah[mt], bl);   // hi*lo
                }
            }
        }
        __syncthreads();
    }

    #pragma unroll
    for (int mt = 0; mt < 2; mt++) {
        const int row = mb + wm * 32 + mt * 16 + g;
        #pragma unroll
        for (int n = 0; n < 8; n++) {
            const int col = nb + wn * 64 + n * 8 + 2 * t;
            if (col + 1 < Nn) {
                *(float2*)(C + (size_t)row * Nn + col) =
                    make_float2(c[mt][n][0], c[mt][n][1]);
                *(float2*)(C + (size_t)(row + 8) * Nn + col) =
                    make_float2(c[mt][n][2], c[mt][n][3]);
            } else if (col < Nn) {
                C[(size_t)row * Nn + col]       = c[mt][n][0];
                C[(size_t)(row + 8) * Nn + col] = c[mt][n][2];
            }
        }
    }
}

// W_o GEMM: grid (N/128, M/128).  min 2 CTAs/SM for inter-CTA overlap.
__global__ __launch_bounds__(256, 2) void gemm3_bf16(const float* __restrict__ A,
                                                     const float* __restrict__ Bm,
                                                     float* __restrict__ C,
                                                     int Kn, int Nn)
{
    gemm3_core(A, Bm, C, Kn, Nn, blockIdx.y * 128, blockIdx.x * 128);
}

// Fused projections: grid.x = 4 (abq n-tiles) + 3 (abkv n-tiles) = 7, grid.y = 32
__global__ __launch_bounds__(256, 2) void proj_fused(const float* __restrict__ x,
                                                     const float* __restrict__ W_abq,
                                                     const float* __restrict__ W_abkv,
                                                     float* __restrict__ abq,
                                                     float* __restrict__ abkv)
{
    const int bx = blockIdx.x;
    if (bx < 4)
        gemm3_core(x, W_abq,  abq,  Dd, NQ,  blockIdx.y * 128, bx * 128);
    else
        gemm3_core(x, W_abkv, abkv, Dd, NKV, blockIdx.y * 128, (bx - 4) * 128);
}

// ============================================================================
// launch
// ============================================================================
extern "C" void kernel_launch(void* const* d_in, const int* in_sizes, int n_in,
                              void* d_out, int out_size)
{
    const float* x      = (const float*)d_in[0];   // [B,T,D]
    const float* W_abq  = (const float*)d_in[1];   // [480,1024]
    const float* W_abkv = (const float*)d_in[2];   // [320,1024]
    const float* W_o    = (const float*)d_in[3];   // [1024,1024]
    float* out = (float*)d_out;                    // [B,T,D]

    float *abq, *abkv, *yb;
    cudaGetSymbolAddress((void**)&abq,  g_abq);
    cudaGetSymbolAddress((void**)&abkv, g_abkv);
    cudaGetSymbolAddress((void**)&yb,   g_y);

    {   // fused x@W_abq^T and x@W_abkv^T  (3x bf16-split)
        dim3 grid(7, M / 128);
        proj_fused<<<grid, 256>>>(x, W_abq, W_abkv, abq, abkv);
    }
    build_qkv<<<M, 128>>>();
    {   // TF32 tensor-core flash attention (unchanged)
        dim3 grid(Bb * NH, Tt / 64);
        attn_mma<<<grid, 128>>>();
    }
    {   // y @ W_o^T -> out  (3x bf16-split)
        dim3 grid(Dd / 128, M / 128);
        gemm3_bf16<<<grid, 256>>>(yb, W_o, out, Dd, Dd);
    }
}